// round 8
// baseline (speedup 1.0000x reference)
#include <cuda_runtime.h>
#include <cuda_bf16.h>
#include <cstdint>

// AdaptiveTokenMixer: out[b,n,:] = sum_k alpha[b,n,k] * x[b,n+k,:]
// Shapes fixed: B=8, N=4096, d=256, K=8.
//
// R8 design: staggered-wait pipelined staging. Each block covers 32 output
// rows; 40 rows staged via 5 separately-committed cp.async batches; compute
// streams through 4 chunks of 8 rows with cp.async.wait_group(3-c), so the
// L2 fill latency is exposed ~once per block instead of once per 16 rows.

constexpr int K_OFF  = 8;                // kernel window
constexpr int D4     = 64;               // d / 4 (float4 columns)
constexpr int NRT    = 32;               // output rows per block
constexpr int BATCH  = 8;                // rows per cp.async commit group
constexpr int NBATCH = 5;                // 5 batches = 40 staged rows
constexpr int SROWS  = NBATCH * BATCH;   // 40 (covers 32 + 7 overlap)
constexpr int NTHR   = 128;
constexpr int NCHUNK = 4;                // 4 compute chunks of 8 rows

// valid_mask dtype probe (JAX bool may arrive as uint8 / int32 / float32).
// lengths >= N/2 guarantees mask[0..3] of batch 0 are all True:
//   uint8:   byte[1] == 1
//   float32: byte[1] == 0, byte[3] == 0x3f
//   int32:   byte[1] == 0, byte[3] == 0x00
__device__ __forceinline__ int probe_mask_mode(const unsigned char* vm) {
    if (vm[1] != 0) return 0;           // uint8
    if (vm[3] == 0x3f) return 2;        // float32
    return 1;                           // int32
}

__device__ __forceinline__ bool mask_at(const unsigned char* vm, int idx, int mode) {
    if (mode == 0) return vm[idx] != 0;
    if (mode == 1) return reinterpret_cast<const int*>(vm)[idx] != 0;
    return reinterpret_cast<const float*>(vm)[idx] != 0.0f;
}

__device__ __forceinline__ void cp_async16(uint32_t dst_smem, const void* src, int src_bytes) {
    asm volatile("cp.async.cg.shared.global [%0], [%1], 16, %2;\n"
                 :: "r"(dst_smem), "l"(src), "r"(src_bytes));
}

__global__ __launch_bounds__(NTHR, 5) void atm_kernel(
    const float* __restrict__ x,
    const float* __restrict__ dt,
    const unsigned char* __restrict__ vm,
    const float* __restrict__ w,
    const float* __restrict__ beta,
    float* __restrict__ out,
    int N)
{
    __shared__ float4 s_x[SROWS][D4];     // 40 KB staged x tile
    __shared__ float4 s_alpha[NRT][2];    // 8 alphas per row as two float4

    const int b   = blockIdx.y;
    const int n0  = blockIdx.x * NRT;
    const int tid = threadIdx.x;

    const float4* __restrict__ xb =
        reinterpret_cast<const float4*>(x) + (size_t)b * N * D4;

    // -------- Stage: 5 batches of 8 rows, committed separately ---------------
    {
        const uint32_t s_base = (uint32_t)__cvta_generic_to_shared(&s_x[0][0]);
        #pragma unroll
        for (int bt = 0; bt < NBATCH; bt++) {
            #pragma unroll
            for (int i = 0; i < BATCH * D4 / NTHR; i++) {     // 4 per thread
                const int idx = bt * BATCH * D4 + tid + i * NTHR;
                const int row = idx >> 6;
                const int col = idx & (D4 - 1);
                const int n   = n0 + row;
                const int ns  = (n < N) ? n : (N - 1);   // clamp address
                const int nb  = (n < N) ? 16 : 0;        // zero-fill OOB
                cp_async16(s_base + (uint32_t)idx * 16u,
                           xb + (size_t)ns * D4 + col, nb);
            }
            asm volatile("cp.async.commit_group;\n" ::: "memory");
        }
    }

    // -------- Alpha softmax for 32 rows (overlaps the async burst) -----------
    if (tid < NRT) {
        const int n = n0 + tid;
        const int mmode = probe_mask_mode(vm);
        const float* dtb = dt + (size_t)b * N;
        const int    mb0 = b * N;

        float wv[K_OFF];
        #pragma unroll
        for (int k = 0; k < K_OFF; k++) wv[k] = w[k];
        float wm = wv[0];
        #pragma unroll
        for (int k = 1; k < K_OFF; k++) wm = fmaxf(wm, wv[k]);
        float wsum = 0.f;
        #pragma unroll
        for (int k = 0; k < K_OFF; k++) { wv[k] = __expf(wv[k] - wm); wsum += wv[k]; }
        const float winv = 1.f / wsum;
        const float bsig = 1.f / (1.f + __expf(-beta[0]));

        const bool  v0  = mask_at(vm, mb0 + n, mmode);
        const float dtn = dtb[n];

        float sc[K_OFF];
        bool  cv[K_OFF];
        #pragma unroll
        for (int k = 0; k < K_OFF; k++) {
            const int  nk  = n + k;
            const bool inb = (nk < N);
            const int  nks = inb ? nk : n;              // OOB-safe index
            const bool cnd = v0 && inb && mask_at(vm, mb0 + nks, mmode);
            const float td = (k == 0) ? 0.f : fmaxf(dtb[nks] - dtn, 0.f);
            cv[k] = cnd;
            sc[k] = cnd ? -td : -1e9f;
        }
        float m = sc[0];
        #pragma unroll
        for (int k = 1; k < K_OFF; k++) m = fmaxf(m, sc[k]);
        float th[K_OFF];
        float es = 0.f;
        #pragma unroll
        for (int k = 0; k < K_OFF; k++) { th[k] = __expf(sc[k] - m); es += th[k]; }
        const float einv = 1.f / es;

        float a[K_OFF];
        float asum = 0.f;
        #pragma unroll
        for (int k = 0; k < K_OFF; k++) {
            const float v = bsig * (wv[k] * winv) + (1.f - bsig) * (th[k] * einv);
            a[k] = cv[k] ? v : 0.f;
            asum += a[k];
        }
        const float ainv = 1.f / fmaxf(asum, 1e-8f);
        #pragma unroll
        for (int k = 0; k < K_OFF; k++) a[k] *= ainv;
        s_alpha[tid][0] = make_float4(a[0], a[1], a[2], a[3]);
        s_alpha[tid][1] = make_float4(a[4], a[5], a[6], a[7]);
    }

    // -------- Compute: 4 chunks of 8 rows, staggered cp.async waits ----------
    const int c = tid & (D4 - 1);
    const int g = tid >> 6;                  // group 0/1 -> 4 rows each per chunk

    float4* __restrict__ ocol =
        reinterpret_cast<float4*>(out) + (size_t)b * N * D4 + c;

#define PROCESS_CHUNK(CH, WAITN)                                               \
    {                                                                          \
        asm volatile("cp.async.wait_group %0;\n" :: "n"(WAITN) : "memory");    \
        __syncthreads();                                                       \
        const int rb = (CH) * BATCH + g * 4;    /* first row, block-local */   \
        float4 win[11];                                                        \
        _Pragma("unroll")                                                      \
        for (int k = 0; k < 11; k++) win[k] = s_x[rb + k][c];                  \
        _Pragma("unroll")                                                      \
        for (int j = 0; j < 4; j++) {                                          \
            const int row = rb + j;                                            \
            const float4 a03 = s_alpha[row][0];                                \
            const float4 a47 = s_alpha[row][1];                                \
            const float al[K_OFF] = { a03.x, a03.y, a03.z, a03.w,              \
                                      a47.x, a47.y, a47.z, a47.w };            \
            float4 acc = make_float4(0.f, 0.f, 0.f, 0.f);                      \
            _Pragma("unroll")                                                  \
            for (int k = 0; k < K_OFF; k++) {                                  \
                const float  a = al[k];                                        \
                const float4 v = win[j + k];                                   \
                acc.x = fmaf(a, v.x, acc.x);                                   \
                acc.y = fmaf(a, v.y, acc.y);                                   \
                acc.z = fmaf(a, v.z, acc.z);                                   \
                acc.w = fmaf(a, v.w, acc.w);                                   \
            }                                                                  \
            ocol[(size_t)(n0 + row) * D4] = acc;                               \
        }                                                                      \
    }

    PROCESS_CHUNK(0, 3)
    PROCESS_CHUNK(1, 2)
    PROCESS_CHUNK(2, 1)
    PROCESS_CHUNK(3, 0)
#undef PROCESS_CHUNK
}

extern "C" void kernel_launch(void* const* d_in, const int* in_sizes, int n_in,
                              void* d_out, int out_size)
{
    // metadata order: x [B,N,d] f32, delta_times [B,N] f32, valid_mask [B,N],
    //                 w [8] f32, beta [1] f32 ; output [B,N,d] f32
    const float*         x    = (const float*)d_in[0];
    const float*         dt   = (const float*)d_in[1];
    const unsigned char* vm   = (const unsigned char*)d_in[2];
    const float*         w    = (const float*)d_in[3];
    const float*         beta = (const float*)d_in[4];
    float*               out  = (float*)d_out;

    const int N = 4096;                       // fixed by problem
    const int BN = in_sizes[1];               // B*N
    const int B = BN / N;                     // 8

    dim3 grid(N / NRT, B);                    // 128 x 8 = 1024 blocks
    atm_kernel<<<grid, NTHR>>>(x, dt, vm, w, beta, out, N);
}

// round 9
// speedup vs baseline: 1.0194x; 1.0194x over previous
#include <cuda_runtime.h>
#include <cuda_bf16.h>
#include <cstdint>

// AdaptiveTokenMixer: out[b,n,:] = sum_k alpha[b,n,k] * x[b,n+k,:]
// Shapes fixed: B=8, N=4096, d=256, K=8.
//
// R8 design: staggered-wait pipelined staging. Each block covers 32 output
// rows; 40 rows staged via 5 separately-committed cp.async batches; compute
// streams through 4 chunks of 8 rows with cp.async.wait_group(3-c), so the
// L2 fill latency is exposed ~once per block instead of once per 16 rows.

constexpr int K_OFF  = 8;                // kernel window
constexpr int D4     = 64;               // d / 4 (float4 columns)
constexpr int NRT    = 32;               // output rows per block
constexpr int BATCH  = 8;                // rows per cp.async commit group
constexpr int NBATCH = 5;                // 5 batches = 40 staged rows
constexpr int SROWS  = NBATCH * BATCH;   // 40 (covers 32 + 7 overlap)
constexpr int NTHR   = 128;
constexpr int NCHUNK = 4;                // 4 compute chunks of 8 rows

// valid_mask dtype probe (JAX bool may arrive as uint8 / int32 / float32).
// lengths >= N/2 guarantees mask[0..3] of batch 0 are all True:
//   uint8:   byte[1] == 1
//   float32: byte[1] == 0, byte[3] == 0x3f
//   int32:   byte[1] == 0, byte[3] == 0x00
__device__ __forceinline__ int probe_mask_mode(const unsigned char* vm) {
    if (vm[1] != 0) return 0;           // uint8
    if (vm[3] == 0x3f) return 2;        // float32
    return 1;                           // int32
}

__device__ __forceinline__ bool mask_at(const unsigned char* vm, int idx, int mode) {
    if (mode == 0) return vm[idx] != 0;
    if (mode == 1) return reinterpret_cast<const int*>(vm)[idx] != 0;
    return reinterpret_cast<const float*>(vm)[idx] != 0.0f;
}

__device__ __forceinline__ void cp_async16(uint32_t dst_smem, const void* src, int src_bytes) {
    asm volatile("cp.async.cg.shared.global [%0], [%1], 16, %2;\n"
                 :: "r"(dst_smem), "l"(src), "r"(src_bytes));
}

__global__ __launch_bounds__(NTHR, 5) void atm_kernel(
    const float* __restrict__ x,
    const float* __restrict__ dt,
    const unsigned char* __restrict__ vm,
    const float* __restrict__ w,
    const float* __restrict__ beta,
    float* __restrict__ out,
    int N)
{
    __shared__ float4 s_x[SROWS][D4];     // 40 KB staged x tile
    __shared__ float4 s_alpha[NRT][2];    // 8 alphas per row as two float4

    const int b   = blockIdx.y;
    const int n0  = blockIdx.x * NRT;
    const int tid = threadIdx.x;

    const float4* __restrict__ xb =
        reinterpret_cast<const float4*>(x) + (size_t)b * N * D4;

    // -------- Stage: 5 batches of 8 rows, committed separately ---------------
    {
        const uint32_t s_base = (uint32_t)__cvta_generic_to_shared(&s_x[0][0]);
        #pragma unroll
        for (int bt = 0; bt < NBATCH; bt++) {
            #pragma unroll
            for (int i = 0; i < BATCH * D4 / NTHR; i++) {     // 4 per thread
                const int idx = bt * BATCH * D4 + tid + i * NTHR;
                const int row = idx >> 6;
                const int col = idx & (D4 - 1);
                const int n   = n0 + row;
                const int ns  = (n < N) ? n : (N - 1);   // clamp address
                const int nb  = (n < N) ? 16 : 0;        // zero-fill OOB
                cp_async16(s_base + (uint32_t)idx * 16u,
                           xb + (size_t)ns * D4 + col, nb);
            }
            asm volatile("cp.async.commit_group;\n" ::: "memory");
        }
    }

    // -------- Alpha softmax for 32 rows (overlaps the async burst) -----------
    if (tid < NRT) {
        const int n = n0 + tid;
        const int mmode = probe_mask_mode(vm);
        const float* dtb = dt + (size_t)b * N;
        const int    mb0 = b * N;

        float wv[K_OFF];
        #pragma unroll
        for (int k = 0; k < K_OFF; k++) wv[k] = w[k];
        float wm = wv[0];
        #pragma unroll
        for (int k = 1; k < K_OFF; k++) wm = fmaxf(wm, wv[k]);
        float wsum = 0.f;
        #pragma unroll
        for (int k = 0; k < K_OFF; k++) { wv[k] = __expf(wv[k] - wm); wsum += wv[k]; }
        const float winv = 1.f / wsum;
        const float bsig = 1.f / (1.f + __expf(-beta[0]));

        const bool  v0  = mask_at(vm, mb0 + n, mmode);
        const float dtn = dtb[n];

        float sc[K_OFF];
        bool  cv[K_OFF];
        #pragma unroll
        for (int k = 0; k < K_OFF; k++) {
            const int  nk  = n + k;
            const bool inb = (nk < N);
            const int  nks = inb ? nk : n;              // OOB-safe index
            const bool cnd = v0 && inb && mask_at(vm, mb0 + nks, mmode);
            const float td = (k == 0) ? 0.f : fmaxf(dtb[nks] - dtn, 0.f);
            cv[k] = cnd;
            sc[k] = cnd ? -td : -1e9f;
        }
        float m = sc[0];
        #pragma unroll
        for (int k = 1; k < K_OFF; k++) m = fmaxf(m, sc[k]);
        float th[K_OFF];
        float es = 0.f;
        #pragma unroll
        for (int k = 0; k < K_OFF; k++) { th[k] = __expf(sc[k] - m); es += th[k]; }
        const float einv = 1.f / es;

        float a[K_OFF];
        float asum = 0.f;
        #pragma unroll
        for (int k = 0; k < K_OFF; k++) {
            const float v = bsig * (wv[k] * winv) + (1.f - bsig) * (th[k] * einv);
            a[k] = cv[k] ? v : 0.f;
            asum += a[k];
        }
        const float ainv = 1.f / fmaxf(asum, 1e-8f);
        #pragma unroll
        for (int k = 0; k < K_OFF; k++) a[k] *= ainv;
        s_alpha[tid][0] = make_float4(a[0], a[1], a[2], a[3]);
        s_alpha[tid][1] = make_float4(a[4], a[5], a[6], a[7]);
    }

    // -------- Compute: 4 chunks of 8 rows, staggered cp.async waits ----------
    const int c = tid & (D4 - 1);
    const int g = tid >> 6;                  // group 0/1 -> 4 rows each per chunk

    float4* __restrict__ ocol =
        reinterpret_cast<float4*>(out) + (size_t)b * N * D4 + c;

#define PROCESS_CHUNK(CH, WAITN)                                               \
    {                                                                          \
        asm volatile("cp.async.wait_group %0;\n" :: "n"(WAITN) : "memory");    \
        __syncthreads();                                                       \
        const int rb = (CH) * BATCH + g * 4;    /* first row, block-local */   \
        float4 win[11];                                                        \
        _Pragma("unroll")                                                      \
        for (int k = 0; k < 11; k++) win[k] = s_x[rb + k][c];                  \
        _Pragma("unroll")                                                      \
        for (int j = 0; j < 4; j++) {                                          \
            const int row = rb + j;                                            \
            const float4 a03 = s_alpha[row][0];                                \
            const float4 a47 = s_alpha[row][1];                                \
            const float al[K_OFF] = { a03.x, a03.y, a03.z, a03.w,              \
                                      a47.x, a47.y, a47.z, a47.w };            \
            float4 acc = make_float4(0.f, 0.f, 0.f, 0.f);                      \
            _Pragma("unroll")                                                  \
            for (int k = 0; k < K_OFF; k++) {                                  \
                const float  a = al[k];                                        \
                const float4 v = win[j + k];                                   \
                acc.x = fmaf(a, v.x, acc.x);                                   \
                acc.y = fmaf(a, v.y, acc.y);                                   \
                acc.z = fmaf(a, v.z, acc.z);                                   \
                acc.w = fmaf(a, v.w, acc.w);                                   \
            }                                                                  \
            ocol[(size_t)(n0 + row) * D4] = acc;                               \
        }                                                                      \
    }

    PROCESS_CHUNK(0, 3)
    PROCESS_CHUNK(1, 2)
    PROCESS_CHUNK(2, 1)
    PROCESS_CHUNK(3, 0)
#undef PROCESS_CHUNK
}

extern "C" void kernel_launch(void* const* d_in, const int* in_sizes, int n_in,
                              void* d_out, int out_size)
{
    // metadata order: x [B,N,d] f32, delta_times [B,N] f32, valid_mask [B,N],
    //                 w [8] f32, beta [1] f32 ; output [B,N,d] f32
    const float*         x    = (const float*)d_in[0];
    const float*         dt   = (const float*)d_in[1];
    const unsigned char* vm   = (const unsigned char*)d_in[2];
    const float*         w    = (const float*)d_in[3];
    const float*         beta = (const float*)d_in[4];
    float*               out  = (float*)d_out;

    const int N = 4096;                       // fixed by problem
    const int BN = in_sizes[1];               // B*N
    const int B = BN / N;                     // 8

    dim3 grid(N / NRT, B);                    // 128 x 8 = 1024 blocks
    atm_kernel<<<grid, NTHR>>>(x, dt, vm, w, beta, out, N);
}

// round 10
// speedup vs baseline: 1.1830x; 1.1604x over previous
#include <cuda_runtime.h>
#include <cuda_bf16.h>
#include <cstdint>

// AdaptiveTokenMixer: out[b,n,:] = sum_k alpha[b,n,k] * x[b,n+k,:]
// Shapes fixed: B=8, N=4096, d=256, K=8.
//
// R10 design: R6 chassis (cp.async-staged 23-row tile, LDS-sourced register
// ring, 63 regs, 8 blocks/SM) with the prologue critical path collapsed:
//  - dt/mask fetched as ONE parallel LDG wavefront into smem (not a serial
//    chain inside the alpha softmax),
//  - alpha computed from smem (29-cyc LDS + ALU only),
//  - all prologue work confined to warp 0 with __syncwarp; the block has a
//    single __syncthreads after cp.async.wait_group 0.

constexpr int K_OFF = 8;               // kernel window
constexpr int D4    = 64;              // d / 4 (float4 columns)
constexpr int RG    = 8;               // output rows per thread-group
constexpr int G     = 2;               // groups per block
constexpr int NR    = RG * G;          // 16 output rows per block
constexpr int SROWS = NR + K_OFF - 1;  // 23 staged rows
constexpr int NTHR  = 128;
constexpr int RING  = 9;               // LDS-sourced register ring

// valid_mask dtype probe (JAX bool may arrive as uint8 / int32 / float32).
// lengths >= N/2 guarantees mask[0..3] of batch 0 are all True:
//   uint8:   byte[1] == 1
//   float32: byte[1] == 0, byte[3] == 0x3f
//   int32:   byte[1] == 0, byte[3] == 0x00
__device__ __forceinline__ int probe_mask_mode(const unsigned char* vm) {
    if (vm[1] != 0) return 0;           // uint8
    if (vm[3] == 0x3f) return 2;        // float32
    return 1;                           // int32
}

__device__ __forceinline__ bool mask_at(const unsigned char* vm, int idx, int mode) {
    if (mode == 0) return vm[idx] != 0;
    if (mode == 1) return reinterpret_cast<const int*>(vm)[idx] != 0;
    return reinterpret_cast<const float*>(vm)[idx] != 0.0f;
}

__device__ __forceinline__ void cp_async16(uint32_t dst_smem, const void* src, int src_bytes) {
    asm volatile("cp.async.cg.shared.global [%0], [%1], 16, %2;\n"
                 :: "r"(dst_smem), "l"(src), "r"(src_bytes));
}

__global__ __launch_bounds__(NTHR, 8) void atm_kernel(
    const float* __restrict__ x,
    const float* __restrict__ dt,
    const unsigned char* __restrict__ vm,
    const float* __restrict__ w,
    const float* __restrict__ beta,
    float* __restrict__ out,
    int N)
{
    __shared__ float4 s_x[SROWS][D4];     // 23 KB staged x tile
    __shared__ float4 s_alpha[NR][2];     // 8 alphas per row as two float4
    __shared__ float  s_dt[SROWS];        // staged delta_times
    __shared__ int    s_vm[SROWS];        // staged mask (0/1)

    const int b   = blockIdx.y;
    const int n0  = blockIdx.x * NR;
    const int tid = threadIdx.x;

    // -------- Stage x: front-batched async copy of rows n0 .. n0+22 ----------
    {
        const float4* __restrict__ xb =
            reinterpret_cast<const float4*>(x) + (size_t)b * N * D4;
        const uint32_t s_base = (uint32_t)__cvta_generic_to_shared(&s_x[0][0]);
        #pragma unroll
        for (int i = 0; i < (SROWS * D4 + NTHR - 1) / NTHR; i++) {
            const int idx = tid + i * NTHR;
            if (idx < SROWS * D4) {
                const int row = idx >> 6;          // /D4
                const int col = idx & (D4 - 1);
                const int n   = n0 + row;
                const int ns  = (n < N) ? n : (N - 1);   // clamp address
                const int nb  = (n < N) ? 16 : 0;        // zero-fill OOB
                cp_async16(s_base + (uint32_t)idx * 16u,
                           xb + (size_t)ns * D4 + col, nb);
            }
        }
        asm volatile("cp.async.commit_group;\n" ::: "memory");
    }

    // -------- Warp 0 prologue: dt/mask wavefront, then alpha from smem -------
    if (tid < 32) {
        // 1) one parallel LDG wavefront: all 23 dt + mask loads in flight at once
        if (tid < SROWS) {
            const int mmode = probe_mask_mode(vm);
            const int n  = n0 + tid;
            const int ns = (n < N) ? n : (N - 1);
            s_dt[tid] = dt[(size_t)b * N + ns];
            s_vm[tid] = (n < N) && mask_at(vm, b * N + ns, mmode) ? 1 : 0;
        }
        __syncwarp();

        // 2) alpha softmax: pure smem/ALU (no global latency in the chain)
        if (tid < NR) {
            float wv[K_OFF];
            #pragma unroll
            for (int k = 0; k < K_OFF; k++) wv[k] = w[k];
            float wm = wv[0];
            #pragma unroll
            for (int k = 1; k < K_OFF; k++) wm = fmaxf(wm, wv[k]);
            float wsum = 0.f;
            #pragma unroll
            for (int k = 0; k < K_OFF; k++) { wv[k] = __expf(wv[k] - wm); wsum += wv[k]; }
            const float winv = 1.f / wsum;
            const float bsig = 1.f / (1.f + __expf(-beta[0]));

            const int   v0  = s_vm[tid];
            const float dtn = s_dt[tid];

            float sc[K_OFF];
            int   cv[K_OFF];
            #pragma unroll
            for (int k = 0; k < K_OFF; k++) {
                const int cnd = v0 & s_vm[tid + k];     // s_vm already 0 for OOB
                const float td = (k == 0) ? 0.f : fmaxf(s_dt[tid + k] - dtn, 0.f);
                cv[k] = cnd;
                sc[k] = cnd ? -td : -1e9f;
            }
            float m = sc[0];
            #pragma unroll
            for (int k = 1; k < K_OFF; k++) m = fmaxf(m, sc[k]);
            float th[K_OFF];
            float es = 0.f;
            #pragma unroll
            for (int k = 0; k < K_OFF; k++) { th[k] = __expf(sc[k] - m); es += th[k]; }
            const float einv = 1.f / es;

            float a[K_OFF];
            float asum = 0.f;
            #pragma unroll
            for (int k = 0; k < K_OFF; k++) {
                const float v = bsig * (wv[k] * winv) + (1.f - bsig) * (th[k] * einv);
                a[k] = cv[k] ? v : 0.f;
                asum += a[k];
            }
            const float ainv = 1.f / fmaxf(asum, 1e-8f);
            #pragma unroll
            for (int k = 0; k < K_OFF; k++) a[k] *= ainv;
            s_alpha[tid][0] = make_float4(a[0], a[1], a[2], a[3]);
            s_alpha[tid][1] = make_float4(a[4], a[5], a[6], a[7]);
        }
    }

    asm volatile("cp.async.wait_group 0;\n" ::: "memory");
    __syncthreads();    // the only block-wide barrier

    // -------- Compute: register ring sourced from smem (29-cyc LDS) ----------
    const int c = tid & (D4 - 1);
    const int g = tid >> 6;
    const int r0 = g * RG;                  // first output row (block-local)

    float4* __restrict__ ocol =
        reinterpret_cast<float4*>(out) + (size_t)b * N * D4 + c;

    float4 win[RING];
    #pragma unroll
    for (int k = 0; k < K_OFF; k++) win[k] = s_x[r0 + k][c];

    #pragma unroll
    for (int r = 0; r < RG; r++) {
        if (r + 1 < RG) win[(r + K_OFF) % RING] = s_x[r0 + r + K_OFF][c];

        const float4 a03 = s_alpha[r0 + r][0];
        const float4 a47 = s_alpha[r0 + r][1];
        const float al[K_OFF] = { a03.x, a03.y, a03.z, a03.w,
                                  a47.x, a47.y, a47.z, a47.w };

        float4 acc = make_float4(0.f, 0.f, 0.f, 0.f);
        #pragma unroll
        for (int k = 0; k < K_OFF; k++) {
            const float  a = al[k];
            const float4 v = win[(r + k) % RING];
            acc.x = fmaf(a, v.x, acc.x);
            acc.y = fmaf(a, v.y, acc.y);
            acc.z = fmaf(a, v.z, acc.z);
            acc.w = fmaf(a, v.w, acc.w);
        }
        ocol[(size_t)(n0 + r0 + r) * D4] = acc;
    }
}

extern "C" void kernel_launch(void* const* d_in, const int* in_sizes, int n_in,
                              void* d_out, int out_size)
{
    // metadata order: x [B,N,d] f32, delta_times [B,N] f32, valid_mask [B,N],
    //                 w [8] f32, beta [1] f32 ; output [B,N,d] f32
    const float*         x    = (const float*)d_in[0];
    const float*         dt   = (const float*)d_in[1];
    const unsigned char* vm   = (const unsigned char*)d_in[2];
    const float*         w    = (const float*)d_in[3];
    const float*         beta = (const float*)d_in[4];
    float*               out  = (float*)d_out;

    const int N = 4096;                       // fixed by problem
    const int BN = in_sizes[1];               // B*N
    const int B = BN / N;                     // 8

    dim3 grid(N / NR, B);                     // 256 x 8 = 2048 blocks
    atm_kernel<<<grid, NTHR>>>(x, dt, vm, w, beta, out, N);
}